// round 11
// baseline (speedup 1.0000x reference)
#include <cuda_runtime.h>
#include <cuda_fp16.h>
#include <cstdint>
#include <math.h>

// Problem constants (fixed by the reference)
#define NN    10000
#define EE    160000
#define CC    16
#define CHW   1024       // C*H*W
#define DE    64         // edge feature dim
#define HID   128        // hidden dim
#define NSEG  (2 * NN)   // (node, dir) segments; dir 0 = out (r<c), 1 = in (r>c)
#define NSCANB ((NSEG + 1023) / 1024)   // 20 scan blocks

// ---------------------------------------------------------------------------
// Scratch (__device__ globals; no allocations allowed)
// ---------------------------------------------------------------------------
__device__ float g_sum_in [NN];
__device__ float g_sum_out[NN];
__device__ float g_exp[EE];
__device__ int   g_row[EE];
__device__ int   g_col[EE];
__device__ int   g_is64;
__device__ int   g_cnt[NSEG];
__device__ int   g_off[NSEG + 1];
__device__ int   g_pos[NSEG];
__device__ int   g_bsum[NSCANB];
__device__ int   g_scol[EE];       // col of sorted edge
__device__ float g_sw  [EE];       // softmax weight of sorted edge
__device__ __align__(16) __half g_xh[NN * CHW];   // fp16 copy of x (20.5 MB)

// ---------------------------------------------------------------------------
// Kernel 1: zero accumulators + (block 0) detect int64 vs int32 edge_index.
// ---------------------------------------------------------------------------
__global__ void zero_kernel(const int* __restrict__ v32) {
    int i = blockIdx.x * blockDim.x + threadIdx.x;
    if (i < NSEG) g_cnt[i] = 0;
    if (i < NN) { g_sum_in[i] = 0.f; g_sum_out[i] = 0.f; }
    if (blockIdx.x == 0 && threadIdx.x < 32) {
        int t = threadIdx.x;
        int nz = 0;
#pragma unroll
        for (int q = 0; q < 4; q++)
            nz |= (v32[2 * (t + q * 32) + 1] != 0);
#pragma unroll
        for (int s = 16; s > 0; s >>= 1)
            nz |= __shfl_xor_sync(0xffffffffu, nz, s);
        if (t == 0) g_is64 = nz ? 0 : 1;
    }
}

// ---------------------------------------------------------------------------
// Kernel 2: decode edge_index + segment histogram (merged)
// ---------------------------------------------------------------------------
__global__ void decode_kernel(const int* __restrict__ v32) {
    int e = blockIdx.x * blockDim.x + threadIdx.x;
    if (e >= EE) return;
    int r, c;
    if (g_is64) { r = v32[2 * e]; c = v32[2 * (EE + e)]; }
    else        { r = v32[e];     c = v32[EE + e]; }
    g_row[e] = r;
    g_col[e] = c;
    if (r != c) atomicAdd(&g_cnt[r * 2 + ((r < c) ? 0 : 1)], 1);
}

// ---------------------------------------------------------------------------
// Kernel 2b: convert x to fp16 (halves the fused-gather L2 traffic)
// ---------------------------------------------------------------------------
__global__ void convx_kernel(const float* __restrict__ x) {
    int i = blockIdx.x * blockDim.x + threadIdx.x;   // over NN*CHW/4
    float4 v = reinterpret_cast<const float4*>(x)[i];
    __half2 a = __floats2half2_rn(v.x, v.y);
    __half2 b = __floats2half2_rn(v.z, v.w);
    uint2 pk;
    pk.x = *reinterpret_cast<unsigned*>(&a);
    pk.y = *reinterpret_cast<unsigned*>(&b);
    reinterpret_cast<uint2*>(g_xh)[i] = pk;
}

// ---------------------------------------------------------------------------
// Kernel 3a: per-block local scan + block sums
// ---------------------------------------------------------------------------
__global__ void scanA_kernel() {      // NSCANB blocks x 1024
    __shared__ int wsum[32];
    const int t = threadIdx.x, lane = t & 31, wid = t >> 5;
    const int idx = blockIdx.x * 1024 + t;
    int v = (idx < NSEG) ? g_cnt[idx] : 0;
    int s = v;
#pragma unroll
    for (int off = 1; off < 32; off <<= 1) {
        int n = __shfl_up_sync(0xffffffffu, s, off);
        if (lane >= off) s += n;
    }
    if (lane == 31) wsum[wid] = s;
    __syncthreads();
    if (wid == 0) {
        int w = wsum[lane];
#pragma unroll
        for (int off = 1; off < 32; off <<= 1) {
            int n = __shfl_up_sync(0xffffffffu, w, off);
            if (lane >= off) w += n;
        }
        wsum[lane] = w;
    }
    __syncthreads();
    int incl = s + ((wid > 0) ? wsum[wid - 1] : 0);
    if (idx < NSEG) g_off[idx] = incl - v;       // local exclusive
    if (t == 1023) g_bsum[blockIdx.x] = incl;    // block total
}

// ---------------------------------------------------------------------------
// Kernel 3b: apply block offsets (each block re-scans the 20 block sums)
// ---------------------------------------------------------------------------
__global__ void scanC_kernel() {
    __shared__ int s_pre[NSCANB + 1];
    const int t = threadIdx.x;
    if (t < 32) {
        int v = (t < NSCANB) ? g_bsum[t] : 0;
        int s = v;
#pragma unroll
        for (int off = 1; off < 32; off <<= 1) {
            int n = __shfl_up_sync(0xffffffffu, s, off);
            if (t >= off) s += n;
        }
        if (t < NSCANB) s_pre[t] = s - v;       // exclusive
        if (t == 31)    s_pre[NSCANB] = s;      // grand total
    }
    __syncthreads();
    int idx = blockIdx.x * blockDim.x + t;
    if (idx < NSEG) {
        int o = g_off[idx] + s_pre[idx >> 10];
        g_off[idx] = o;
        g_pos[idx] = o;
    }
    if (idx == 0) g_off[NSEG] = s_pre[NSCANB];
}

// ---------------------------------------------------------------------------
// Kernel 4: edge MLP on the TENSOR pipe (mma.m16n8k16 f16->f32).
// ---------------------------------------------------------------------------
#define EPB 256
#define EAS 72                      // half stride per row (144B)
#define SM_W1T  0                   // [128][72] halfs = 18432 B
#define SM_EAS  18432               // [256][72] halfs = 36864 B
#define SM_B1   55296               // 128 floats
#define SM_W2   55808               // 128 floats
#define SM_B2   56320               // 1 float
#define MLP_SMEM_BYTES 56448

__device__ __forceinline__ unsigned smem_u32(const void* p) {
    return (unsigned)__cvta_generic_to_shared(p);
}

__global__ void __launch_bounds__(256, 2)
mlp_kernel(const float* __restrict__ edge_attr,
           const float* __restrict__ W1,
           const float* __restrict__ b1,
           const float* __restrict__ W2,
           const float* __restrict__ b2,
           float* __restrict__ logits,
           int write_logits) {
    extern __shared__ char smemraw[];
    __half* W1T = reinterpret_cast<__half*>(smemraw + SM_W1T);
    __half* eas = reinterpret_cast<__half*>(smemraw + SM_EAS);
    float*  b1s = reinterpret_cast<float*>(smemraw + SM_B1);
    float*  W2s = reinterpret_cast<float*>(smemraw + SM_W2);
    float*  b2s = reinterpret_cast<float*>(smemraw + SM_B2);

    const int t = threadIdx.x;

    // Stage W1 transposed as fp16: W1T[n][k] = W1[k][n]
    for (int i = t; i < DE * HID; i += 256) {
        int k = i >> 7, n = i & 127;
        W1T[n * EAS + k] = __float2half_rn(W1[i]);
    }
    if (t < 128) { b1s[t] = b1[t]; W2s[t] = W2[t]; }
    if (t == 0)  b2s[0] = b2[0];

    // Stage 256 edges of edge_attr as fp16, stride-72 rows
    const float4* ea4 = reinterpret_cast<const float4*>(
        edge_attr + (size_t)blockIdx.x * EPB * DE);
    for (int i = t; i < EPB * DE / 4; i += 256) {
        float4 v = ea4[i];
        int ed = i >> 4;            // 16 float4 per edge
        int k4 = i & 15;
        __half2 h01 = __floats2half2_rn(v.x, v.y);
        __half2 h23 = __floats2half2_rn(v.z, v.w);
        uint2 pk;
        pk.x = *reinterpret_cast<unsigned*>(&h01);
        pk.y = *reinterpret_cast<unsigned*>(&h23);
        *reinterpret_cast<uint2*>(eas + ed * EAS + k4 * 4) = pk;
    }
    __syncthreads();

    const int wid  = t >> 5;
    const int lane = t & 31;
    const int gid  = lane >> 2;     // 0..7
    const int tig  = lane & 3;      // 0..3
    const int ebase = wid * 32;     // this warp's 32 edges (2 m16-tiles)

    // Load A fragments: [2 tiles][4 k-chunks][4 regs] via ldmatrix.x4
    unsigned afr[2][4][4];
    const int arow  = ebase + (lane & 15);
    const int acolh = (lane >> 4) * 8;
#pragma unroll
    for (int tile = 0; tile < 2; tile++) {
#pragma unroll
        for (int kc = 0; kc < 4; kc++) {
            unsigned addr = smem_u32(
                &eas[(arow + tile * 16) * EAS + kc * 16 + acolh]);
            asm volatile(
                "ldmatrix.sync.aligned.m8n8.x4.shared.b16 {%0,%1,%2,%3}, [%4];"
                : "=r"(afr[tile][kc][0]), "=r"(afr[tile][kc][1]),
                  "=r"(afr[tile][kc][2]), "=r"(afr[tile][kc][3])
                : "r"(addr));
        }
    }

    float lp[4] = {0.f, 0.f, 0.f, 0.f};   // [tile*2 + rowhalf]

#pragma unroll 4
    for (int nt = 0; nt < 16; nt++) {
        // B fragments for this n-tile: conflict-free LDS.32 from W1T
        const __half* wb = &W1T[(nt * 8 + gid) * EAS];
        unsigned bfr[4][2];
#pragma unroll
        for (int kc = 0; kc < 4; kc++) {
            bfr[kc][0] = *reinterpret_cast<const unsigned*>(
                wb + kc * 16 + 2 * tig);
            bfr[kc][1] = *reinterpret_cast<const unsigned*>(
                wb + kc * 16 + 2 * tig + 8);
        }
        const int colb = nt * 8 + tig * 2;
        float b1a = b1s[colb],  b1b = b1s[colb + 1];
        float w2a = W2s[colb],  w2b = W2s[colb + 1];

#pragma unroll
        for (int tile = 0; tile < 2; tile++) {
            float c0 = 0.f, c1 = 0.f, c2 = 0.f, c3 = 0.f;
#pragma unroll
            for (int kc = 0; kc < 4; kc++) {
                asm volatile(
                    "mma.sync.aligned.m16n8k16.row.col.f32.f16.f16.f32 "
                    "{%0,%1,%2,%3}, {%4,%5,%6,%7}, {%8,%9}, {%0,%1,%2,%3};"
                    : "+f"(c0), "+f"(c1), "+f"(c2), "+f"(c3)
                    : "r"(afr[tile][kc][0]), "r"(afr[tile][kc][1]),
                      "r"(afr[tile][kc][2]), "r"(afr[tile][kc][3]),
                      "r"(bfr[kc][0]), "r"(bfr[kc][1]));
            }
            lp[tile*2+0] += fmaxf(c0 + b1a, 0.f) * w2a
                          + fmaxf(c1 + b1b, 0.f) * w2b;
            lp[tile*2+1] += fmaxf(c2 + b1a, 0.f) * w2a
                          + fmaxf(c3 + b1b, 0.f) * w2b;
        }
    }

    // Reduce across the 4-thread quad (tig dimension)
#pragma unroll
    for (int s = 1; s <= 2; s <<= 1) {
#pragma unroll
        for (int m = 0; m < 4; m++)
            lp[m] += __shfl_xor_sync(0xffffffffu, lp[m], s);
    }

    if (tig == 0) {
        float bb = b2s[0];
#pragma unroll
        for (int tile = 0; tile < 2; tile++) {
#pragma unroll
            for (int h = 0; h < 2; h++) {
                int e = blockIdx.x * EPB + ebase + tile * 16 + h * 8 + gid;
                float logit = lp[tile * 2 + h] + bb;
                if (write_logits) logits[e] = logit;
                float ex = expf(logit);
                g_exp[e] = ex;
                int r = g_row[e], c = g_col[e];
                if (r < c)      atomicAdd(&g_sum_out[r], ex);
                else if (r > c) atomicAdd(&g_sum_in[r],  ex);
            }
        }
    }
}

// ---------------------------------------------------------------------------
// Kernel 5: fill CSR lists with final softmax weights (sums ready post-MLP)
// ---------------------------------------------------------------------------
__global__ void fill_kernel() {
    int e = blockIdx.x * blockDim.x + threadIdx.x;
    if (e >= EE) return;
    int r = g_row[e], c = g_col[e];
    if (r == c) return;
    int dirin = (r > c);
    int seg = r * 2 + dirin;
    int pos = atomicAdd(&g_pos[seg], 1);
    float sum = dirin ? g_sum_in[r] : g_sum_out[r];
    g_scol[pos] = c;
    g_sw[pos]   = g_exp[e] / fmaxf(sum, 1e-30f);
}

// ---------------------------------------------------------------------------
// Kernel 6: fused gather-aggregate + 1x1 conv. One block per node.
// Gather reads fp16 x (halved L2 traffic); accumulation fp32; conv reads
// the exact fp32 x for the x-term.
// ---------------------------------------------------------------------------
#define ECHUNK 128

__global__ void __launch_bounds__(256)
fused_kernel(const float* __restrict__ x,
             const float* __restrict__ Wn,
             const float* __restrict__ bn,
             float* __restrict__ out) {
    __shared__ float s_fo[CHW];      // flow_out
    __shared__ float s_fi[CHW];      // flow_in
    __shared__ float WsT[48 * 16];   // WsT[cc][o] = Wn[o*48+cc]
    __shared__ float bs[16];
    __shared__ int   s_ec[ECHUNK];
    __shared__ float s_ew[ECHUNK];

    const int n = blockIdx.x;
    const int t = threadIdx.x;

    for (int i = t; i < 768; i += 256) {
        int o = i / 48, cc = i % 48;
        WsT[cc * 16 + o] = Wn[i];
    }
    if (t < 16) bs[t] = bn[t];

    const int off0 = g_off[2 * n];
    const int off1 = g_off[2 * n + 1];
    const int off2 = g_off[2 * n + 2];

    const uint2* xh = reinterpret_cast<const uint2*>(g_xh);

    float4 accO = make_float4(0.f, 0.f, 0.f, 0.f);
    float4 accI = make_float4(0.f, 0.f, 0.f, 0.f);

    // dir 0: outgoing flow (r < c)
    for (int base = off0; base < off1; base += ECHUNK) {
        int m = min(ECHUNK, off1 - base);
        __syncthreads();
        for (int j = t; j < m; j += 256) {
            s_ec[j] = g_scol[base + j];
            s_ew[j] = g_sw[base + j];
        }
        __syncthreads();
#pragma unroll 4
        for (int j = 0; j < m; j++) {
            float w = s_ew[j];
            uint2 hv = __ldg(&xh[(size_t)s_ec[j] * 256 + t]);
            __half2 h0 = *reinterpret_cast<__half2*>(&hv.x);
            __half2 h1 = *reinterpret_cast<__half2*>(&hv.y);
            float2 f0 = __half22float2(h0);
            float2 f1 = __half22float2(h1);
            accO.x += w * f0.x; accO.y += w * f0.y;
            accO.z += w * f1.x; accO.w += w * f1.y;
        }
    }
    // dir 1: incoming flow (r > c)
    for (int base = off1; base < off2; base += ECHUNK) {
        int m = min(ECHUNK, off2 - base);
        __syncthreads();
        for (int j = t; j < m; j += 256) {
            s_ec[j] = g_scol[base + j];
            s_ew[j] = g_sw[base + j];
        }
        __syncthreads();
#pragma unroll 4
        for (int j = 0; j < m; j++) {
            float w = s_ew[j];
            uint2 hv = __ldg(&xh[(size_t)s_ec[j] * 256 + t]);
            __half2 h0 = *reinterpret_cast<__half2*>(&hv.x);
            __half2 h1 = *reinterpret_cast<__half2*>(&hv.y);
            float2 f0 = __half22float2(h0);
            float2 f1 = __half22float2(h1);
            accI.x += w * f0.x; accI.y += w * f0.y;
            accI.z += w * f1.x; accI.w += w * f1.y;
        }
    }

    __syncthreads();
    reinterpret_cast<float4*>(s_fo)[t] = accO;
    reinterpret_cast<float4*>(s_fi)[t] = accI;
    __syncthreads();

    const int hw = t & 63;
    const int og = t >> 6;

    float acc[4];
#pragma unroll
    for (int j = 0; j < 4; j++) acc[j] = bs[og * 4 + j];

    const float* xb = x + (size_t)n * CHW;
#pragma unroll 4
    for (int cc = 0; cc < 16; cc++) {
        float vx = __ldg(&xb[cc * 64 + hw]);
        float vi = s_fi[cc * 64 + hw];
        float vo = s_fo[cc * 64 + hw];
        float4 wx = reinterpret_cast<const float4*>(&WsT[(cc)      * 16])[og];
        float4 wi = reinterpret_cast<const float4*>(&WsT[(16 + cc) * 16])[og];
        float4 wo = reinterpret_cast<const float4*>(&WsT[(32 + cc) * 16])[og];
        acc[0] += vx * wx.x + vi * wi.x + vo * wo.x;
        acc[1] += vx * wx.y + vi * wi.y + vo * wo.y;
        acc[2] += vx * wx.z + vi * wi.z + vo * wo.z;
        acc[3] += vx * wx.w + vi * wi.w + vo * wo.w;
    }

    float* ob = out + (size_t)n * CHW;
#pragma unroll
    for (int j = 0; j < 4; j++)
        ob[(og * 4 + j) * 64 + hw] = acc[j];
}

// ---------------------------------------------------------------------------
// Launch (default stream; sequentially ordered; graph-capturable)
// MLP stays the 4th launch so ncu samples it.
// ---------------------------------------------------------------------------
extern "C" void kernel_launch(void* const* d_in, const int* in_sizes, int n_in,
                              void* d_out, int out_size) {
    const float* x         = (const float*)d_in[0];
    const float* edge_attr = (const float*)d_in[1];
    const float* W1        = (const float*)d_in[2];
    const float* b1        = (const float*)d_in[3];
    const float* W2        = (const float*)d_in[4];
    const float* b2        = (const float*)d_in[5];
    const float* Wn        = (const float*)d_in[6];
    const float* bn        = (const float*)d_in[7];
    const int*   ei32      = (const int*)d_in[8];

    float* out    = (float*)d_out;
    const int write_logits = (out_size >= NN * CHW + EE);
    float* logits = out + (size_t)NN * CHW;

    cudaFuncSetAttribute(mlp_kernel,
                         cudaFuncAttributeMaxDynamicSharedMemorySize,
                         MLP_SMEM_BYTES);

    const int EB = (EE + 255) / 256;

    zero_kernel<<<(NSEG + 255) / 256, 256>>>(ei32);
    decode_kernel<<<EB, 256>>>(ei32);
    convx_kernel<<<NN * CHW / 4 / 256, 256>>>(x);
    mlp_kernel<<<EE / EPB, 256, MLP_SMEM_BYTES>>>(edge_attr, W1, b1, W2, b2,
                                                  logits, write_logits);
    scanA_kernel<<<NSCANB, 1024>>>();
    scanC_kernel<<<(NSEG + 255) / 256, 256>>>();
    fill_kernel<<<EB, 256>>>();
    fused_kernel<<<NN, 256>>>(x, Wn, bn, out);
}

// round 12
// speedup vs baseline: 1.0251x; 1.0251x over previous
#include <cuda_runtime.h>
#include <cuda_fp16.h>
#include <cstdint>
#include <math.h>

// Problem constants (fixed by the reference)
#define NN    10000
#define EE    160000
#define CC    16
#define CHW   1024       // C*H*W
#define DE    64         // edge feature dim
#define HID   128        // hidden dim
#define NSEG  (2 * NN)   // (node, dir) segments; dir 0 = out (r<c), 1 = in (r>c)
#define NSCANB ((NSEG + 1023) / 1024)   // 20 scan blocks

// ---------------------------------------------------------------------------
// Scratch (__device__ globals; no allocations allowed)
// ---------------------------------------------------------------------------
__device__ float g_sum_in [NN];
__device__ float g_sum_out[NN];
__device__ float g_exp[EE];
__device__ int   g_row[EE];
__device__ int   g_col[EE];
__device__ int   g_is64;
__device__ int   g_cnt[NSEG];
__device__ int   g_off[NSEG + 1];
__device__ int   g_pos[NSEG];
__device__ int   g_bsum[NSCANB];
__device__ int   g_scol[EE];       // col of sorted edge
__device__ float g_sw  [EE];       // softmax weight of sorted edge
__device__ __align__(16) __half g_xh[NN * CHW];   // fp16 copy of x (20.5 MB)

// ---------------------------------------------------------------------------
// Kernel 1: zero accumulators + (block 0) detect int64 vs int32 edge_index.
// ---------------------------------------------------------------------------
__global__ void zero_kernel(const int* __restrict__ v32) {
    int i = blockIdx.x * blockDim.x + threadIdx.x;
    if (i < NSEG) g_cnt[i] = 0;
    if (i < NN) { g_sum_in[i] = 0.f; g_sum_out[i] = 0.f; }
    if (blockIdx.x == 0 && threadIdx.x < 32) {
        int t = threadIdx.x;
        int nz = 0;
#pragma unroll
        for (int q = 0; q < 4; q++)
            nz |= (v32[2 * (t + q * 32) + 1] != 0);
#pragma unroll
        for (int s = 16; s > 0; s >>= 1)
            nz |= __shfl_xor_sync(0xffffffffu, nz, s);
        if (t == 0) g_is64 = nz ? 0 : 1;
    }
}

// ---------------------------------------------------------------------------
// Kernel 2: decode edge_index + segment histogram (merged)
// ---------------------------------------------------------------------------
__global__ void decode_kernel(const int* __restrict__ v32) {
    int e = blockIdx.x * blockDim.x + threadIdx.x;
    if (e >= EE) return;
    int r, c;
    if (g_is64) { r = v32[2 * e]; c = v32[2 * (EE + e)]; }
    else        { r = v32[e];     c = v32[EE + e]; }
    g_row[e] = r;
    g_col[e] = c;
    if (r != c) atomicAdd(&g_cnt[r * 2 + ((r < c) ? 0 : 1)], 1);
}

// ---------------------------------------------------------------------------
// Kernel 2b: convert x to fp16 (halves the fused-gather L2 traffic)
// ---------------------------------------------------------------------------
__global__ void convx_kernel(const float* __restrict__ x) {
    int i = blockIdx.x * blockDim.x + threadIdx.x;   // over NN*CHW/4
    float4 v = reinterpret_cast<const float4*>(x)[i];
    __half2 a = __floats2half2_rn(v.x, v.y);
    __half2 b = __floats2half2_rn(v.z, v.w);
    uint2 pk;
    pk.x = *reinterpret_cast<unsigned*>(&a);
    pk.y = *reinterpret_cast<unsigned*>(&b);
    reinterpret_cast<uint2*>(g_xh)[i] = pk;
}

// ---------------------------------------------------------------------------
// Kernel 3a: per-block local scan + block sums
// ---------------------------------------------------------------------------
__global__ void scanA_kernel() {      // NSCANB blocks x 1024
    __shared__ int wsum[32];
    const int t = threadIdx.x, lane = t & 31, wid = t >> 5;
    const int idx = blockIdx.x * 1024 + t;
    int v = (idx < NSEG) ? g_cnt[idx] : 0;
    int s = v;
#pragma unroll
    for (int off = 1; off < 32; off <<= 1) {
        int n = __shfl_up_sync(0xffffffffu, s, off);
        if (lane >= off) s += n;
    }
    if (lane == 31) wsum[wid] = s;
    __syncthreads();
    if (wid == 0) {
        int w = wsum[lane];
#pragma unroll
        for (int off = 1; off < 32; off <<= 1) {
            int n = __shfl_up_sync(0xffffffffu, w, off);
            if (lane >= off) w += n;
        }
        wsum[lane] = w;
    }
    __syncthreads();
    int incl = s + ((wid > 0) ? wsum[wid - 1] : 0);
    if (idx < NSEG) g_off[idx] = incl - v;       // local exclusive
    if (t == 1023) g_bsum[blockIdx.x] = incl;    // block total
}

// ---------------------------------------------------------------------------
// Kernel 3b: apply block offsets (each block re-scans the 20 block sums)
// ---------------------------------------------------------------------------
__global__ void scanC_kernel() {
    __shared__ int s_pre[NSCANB + 1];
    const int t = threadIdx.x;
    if (t < 32) {
        int v = (t < NSCANB) ? g_bsum[t] : 0;
        int s = v;
#pragma unroll
        for (int off = 1; off < 32; off <<= 1) {
            int n = __shfl_up_sync(0xffffffffu, s, off);
            if (t >= off) s += n;
        }
        if (t < NSCANB) s_pre[t] = s - v;       // exclusive
        if (t == 31)    s_pre[NSCANB] = s;      // grand total
    }
    __syncthreads();
    int idx = blockIdx.x * blockDim.x + t;
    if (idx < NSEG) {
        int o = g_off[idx] + s_pre[idx >> 10];
        g_off[idx] = o;
        g_pos[idx] = o;
    }
    if (idx == 0) g_off[NSEG] = s_pre[NSCANB];
}

// ---------------------------------------------------------------------------
// Kernel 4: edge MLP on the TENSOR pipe (mma.m16n8k16 f16->f32).
// kc accumulation split into 2 independent chains per tile (4 chains in
// flight with tile interleave) to break MMA latency serialization.
// ---------------------------------------------------------------------------
#define EPB 256
#define EAS 72                      // half stride per row (144B)
#define SM_W1T  0                   // [128][72] halfs = 18432 B
#define SM_EAS  18432               // [256][72] halfs = 36864 B
#define SM_B1   55296               // 128 floats
#define SM_W2   55808               // 128 floats
#define SM_B2   56320               // 1 float
#define MLP_SMEM_BYTES 56448

__device__ __forceinline__ unsigned smem_u32(const void* p) {
    return (unsigned)__cvta_generic_to_shared(p);
}

__global__ void __launch_bounds__(256, 2)
mlp_kernel(const float* __restrict__ edge_attr,
           const float* __restrict__ W1,
           const float* __restrict__ b1,
           const float* __restrict__ W2,
           const float* __restrict__ b2,
           float* __restrict__ logits,
           int write_logits) {
    extern __shared__ char smemraw[];
    __half* W1T = reinterpret_cast<__half*>(smemraw + SM_W1T);
    __half* eas = reinterpret_cast<__half*>(smemraw + SM_EAS);
    float*  b1s = reinterpret_cast<float*>(smemraw + SM_B1);
    float*  W2s = reinterpret_cast<float*>(smemraw + SM_W2);
    float*  b2s = reinterpret_cast<float*>(smemraw + SM_B2);

    const int t = threadIdx.x;

    // Stage W1 transposed as fp16: W1T[n][k] = W1[k][n]
    for (int i = t; i < DE * HID; i += 256) {
        int k = i >> 7, n = i & 127;
        W1T[n * EAS + k] = __float2half_rn(W1[i]);
    }
    if (t < 128) { b1s[t] = b1[t]; W2s[t] = W2[t]; }
    if (t == 0)  b2s[0] = b2[0];

    // Stage 256 edges of edge_attr as fp16, stride-72 rows
    const float4* ea4 = reinterpret_cast<const float4*>(
        edge_attr + (size_t)blockIdx.x * EPB * DE);
    for (int i = t; i < EPB * DE / 4; i += 256) {
        float4 v = ea4[i];
        int ed = i >> 4;            // 16 float4 per edge
        int k4 = i & 15;
        __half2 h01 = __floats2half2_rn(v.x, v.y);
        __half2 h23 = __floats2half2_rn(v.z, v.w);
        uint2 pk;
        pk.x = *reinterpret_cast<unsigned*>(&h01);
        pk.y = *reinterpret_cast<unsigned*>(&h23);
        *reinterpret_cast<uint2*>(eas + ed * EAS + k4 * 4) = pk;
    }
    __syncthreads();

    const int wid  = t >> 5;
    const int lane = t & 31;
    const int gid  = lane >> 2;     // 0..7
    const int tig  = lane & 3;      // 0..3
    const int ebase = wid * 32;     // this warp's 32 edges (2 m16-tiles)

    // Load A fragments: [2 tiles][4 k-chunks][4 regs] via ldmatrix.x4
    unsigned afr[2][4][4];
    const int arow  = ebase + (lane & 15);
    const int acolh = (lane >> 4) * 8;
#pragma unroll
    for (int tile = 0; tile < 2; tile++) {
#pragma unroll
        for (int kc = 0; kc < 4; kc++) {
            unsigned addr = smem_u32(
                &eas[(arow + tile * 16) * EAS + kc * 16 + acolh]);
            asm volatile(
                "ldmatrix.sync.aligned.m8n8.x4.shared.b16 {%0,%1,%2,%3}, [%4];"
                : "=r"(afr[tile][kc][0]), "=r"(afr[tile][kc][1]),
                  "=r"(afr[tile][kc][2]), "=r"(afr[tile][kc][3])
                : "r"(addr));
        }
    }

    float lp[4] = {0.f, 0.f, 0.f, 0.f};   // [tile*2 + rowhalf]

#pragma unroll 4
    for (int nt = 0; nt < 16; nt++) {
        // B fragments for this n-tile: conflict-free LDS.32 from W1T
        const __half* wb = &W1T[(nt * 8 + gid) * EAS];
        unsigned bfr[4][2];
#pragma unroll
        for (int kc = 0; kc < 4; kc++) {
            bfr[kc][0] = *reinterpret_cast<const unsigned*>(
                wb + kc * 16 + 2 * tig);
            bfr[kc][1] = *reinterpret_cast<const unsigned*>(
                wb + kc * 16 + 2 * tig + 8);
        }
        const int colb = nt * 8 + tig * 2;
        float b1a = b1s[colb],  b1b = b1s[colb + 1];
        float w2a = W2s[colb],  w2b = W2s[colb + 1];

#pragma unroll
        for (int tile = 0; tile < 2; tile++) {
            // two independent kc-chains per tile -> 2x MMA parallelism
            float a0 = 0.f, a1 = 0.f, a2 = 0.f, a3 = 0.f;   // kc 0,1
            float d0 = 0.f, d1 = 0.f, d2 = 0.f, d3 = 0.f;   // kc 2,3
#pragma unroll
            for (int kc = 0; kc < 2; kc++) {
                asm volatile(
                    "mma.sync.aligned.m16n8k16.row.col.f32.f16.f16.f32 "
                    "{%0,%1,%2,%3}, {%4,%5,%6,%7}, {%8,%9}, {%0,%1,%2,%3};"
                    : "+f"(a0), "+f"(a1), "+f"(a2), "+f"(a3)
                    : "r"(afr[tile][kc][0]), "r"(afr[tile][kc][1]),
                      "r"(afr[tile][kc][2]), "r"(afr[tile][kc][3]),
                      "r"(bfr[kc][0]), "r"(bfr[kc][1]));
                asm volatile(
                    "mma.sync.aligned.m16n8k16.row.col.f32.f16.f16.f32 "
                    "{%0,%1,%2,%3}, {%4,%5,%6,%7}, {%8,%9}, {%0,%1,%2,%3};"
                    : "+f"(d0), "+f"(d1), "+f"(d2), "+f"(d3)
                    : "r"(afr[tile][kc + 2][0]), "r"(afr[tile][kc + 2][1]),
                      "r"(afr[tile][kc + 2][2]), "r"(afr[tile][kc + 2][3]),
                      "r"(bfr[kc + 2][0]), "r"(bfr[kc + 2][1]));
            }
            float c0 = a0 + d0, c1 = a1 + d1;
            float c2 = a2 + d2, c3 = a3 + d3;
            lp[tile*2+0] += fmaxf(c0 + b1a, 0.f) * w2a
                          + fmaxf(c1 + b1b, 0.f) * w2b;
            lp[tile*2+1] += fmaxf(c2 + b1a, 0.f) * w2a
                          + fmaxf(c3 + b1b, 0.f) * w2b;
        }
    }

    // Reduce across the 4-thread quad (tig dimension)
#pragma unroll
    for (int s = 1; s <= 2; s <<= 1) {
#pragma unroll
        for (int m = 0; m < 4; m++)
            lp[m] += __shfl_xor_sync(0xffffffffu, lp[m], s);
    }

    if (tig == 0) {
        float bb = b2s[0];
#pragma unroll
        for (int tile = 0; tile < 2; tile++) {
#pragma unroll
            for (int h = 0; h < 2; h++) {
                int e = blockIdx.x * EPB + ebase + tile * 16 + h * 8 + gid;
                float logit = lp[tile * 2 + h] + bb;
                if (write_logits) logits[e] = logit;
                float ex = expf(logit);
                g_exp[e] = ex;
                int r = g_row[e], c = g_col[e];
                if (r < c)      atomicAdd(&g_sum_out[r], ex);
                else if (r > c) atomicAdd(&g_sum_in[r],  ex);
            }
        }
    }
}

// ---------------------------------------------------------------------------
// Kernel 5: fill CSR lists with final softmax weights (sums ready post-MLP)
// ---------------------------------------------------------------------------
__global__ void fill_kernel() {
    int e = blockIdx.x * blockDim.x + threadIdx.x;
    if (e >= EE) return;
    int r = g_row[e], c = g_col[e];
    if (r == c) return;
    int dirin = (r > c);
    int seg = r * 2 + dirin;
    int pos = atomicAdd(&g_pos[seg], 1);
    float sum = dirin ? g_sum_in[r] : g_sum_out[r];
    g_scol[pos] = c;
    g_sw[pos]   = g_exp[e] / fmaxf(sum, 1e-30f);
}

// ---------------------------------------------------------------------------
// Kernel 6: fused gather-aggregate + 1x1 conv. One block per node,
// 128 THREADS (4 warps, ~7K regs) -> ~2x blocks/SM vs 256-thread version,
// doubling independent edge gather streams per SM (latency-bound fix).
// Each thread owns a 16B fp16 slice (one uint4 = 8 halves) of the node tile.
// ---------------------------------------------------------------------------
#define ECHUNK 128

__global__ void __launch_bounds__(128)
fused_kernel(const float* __restrict__ x,
             const float* __restrict__ Wn,
             const float* __restrict__ bn,
             float* __restrict__ out) {
    __shared__ float s_fo[CHW];      // flow_out
    __shared__ float s_fi[CHW];      // flow_in
    __shared__ float WsT[48 * 16];   // WsT[cc][o] = Wn[o*48+cc]
    __shared__ float bs[16];
    __shared__ int   s_ec[ECHUNK];
    __shared__ float s_ew[ECHUNK];

    const int n = blockIdx.x;
    const int t = threadIdx.x;

    for (int i = t; i < 768; i += 128) {
        int o = i / 48, cc = i % 48;
        WsT[cc * 16 + o] = Wn[i];
    }
    if (t < 16) bs[t] = bn[t];

    const int off0 = g_off[2 * n];
    const int off1 = g_off[2 * n + 1];
    const int off2 = g_off[2 * n + 2];

    // node tile = 2048 halves = 128 uint4; thread t owns halves [8t, 8t+8)
    const uint4* xh = reinterpret_cast<const uint4*>(g_xh);

    float accO[8] = {0,0,0,0,0,0,0,0};
    float accI[8] = {0,0,0,0,0,0,0,0};

#pragma unroll 1
    for (int dir = 0; dir < 2; dir++) {
        const int lo = dir ? off1 : off0;
        const int hi = dir ? off2 : off1;
        float* acc = dir ? accI : accO;

        for (int base = lo; base < hi; base += ECHUNK) {
            int m = min(ECHUNK, hi - base);
            __syncthreads();
            if (t < m) {                       // m <= 128: single pass
                s_ec[t] = g_scol[base + t];
                s_ew[t] = g_sw[base + t];
            }
            __syncthreads();
#pragma unroll 4
            for (int j = 0; j < m; j++) {
                float w = s_ew[j];
                uint4 hv = __ldg(&xh[(size_t)s_ec[j] * 128 + t]);
                unsigned u[4] = {hv.x, hv.y, hv.z, hv.w};
#pragma unroll
                for (int q = 0; q < 4; q++) {
                    __half2 h = *reinterpret_cast<__half2*>(&u[q]);
                    float2 f = __half22float2(h);
                    acc[q*2]   += w * f.x;
                    acc[q*2+1] += w * f.y;
                }
            }
        }
    }

    __syncthreads();
#pragma unroll
    for (int q = 0; q < 2; q++) {
        reinterpret_cast<float4*>(s_fo)[2*t+q] =
            make_float4(accO[q*4], accO[q*4+1], accO[q*4+2], accO[q*4+3]);
        reinterpret_cast<float4*>(s_fi)[2*t+q] =
            make_float4(accI[q*4], accI[q*4+1], accI[q*4+2], accI[q*4+3]);
    }
    __syncthreads();

    // Conv: hw = t&63; og2 = t>>6 selects output channels [og2*8, og2*8+8)
    const int hw  = t & 63;
    const int og2 = t >> 6;

    float acc[8];
#pragma unroll
    for (int j = 0; j < 8; j++) acc[j] = bs[og2 * 8 + j];

    const float* xb = x + (size_t)n * CHW;
#pragma unroll 4
    for (int cc = 0; cc < 16; cc++) {
        float vx = __ldg(&xb[cc * 64 + hw]);
        float vi = s_fi[cc * 64 + hw];
        float vo = s_fo[cc * 64 + hw];
#pragma unroll
        for (int g = 0; g < 2; g++) {
            float4 wx = reinterpret_cast<const float4*>(
                &WsT[(cc)      * 16])[og2 * 2 + g];
            float4 wi = reinterpret_cast<const float4*>(
                &WsT[(16 + cc) * 16])[og2 * 2 + g];
            float4 wo = reinterpret_cast<const float4*>(
                &WsT[(32 + cc) * 16])[og2 * 2 + g];
            acc[g*4+0] += vx * wx.x + vi * wi.x + vo * wo.x;
            acc[g*4+1] += vx * wx.y + vi * wi.y + vo * wo.y;
            acc[g*4+2] += vx * wx.z + vi * wi.z + vo * wo.z;
            acc[g*4+3] += vx * wx.w + vi * wi.w + vo * wo.w;
        }
    }

    float* ob = out + (size_t)n * CHW;
#pragma unroll
    for (int j = 0; j < 8; j++)
        ob[(og2 * 8 + j) * 64 + hw] = acc[j];
}

// ---------------------------------------------------------------------------
// Launch (default stream; sequentially ordered; graph-capturable)
// MLP stays the 4th launch so ncu samples it.
// ---------------------------------------------------------------------------
extern "C" void kernel_launch(void* const* d_in, const int* in_sizes, int n_in,
                              void* d_out, int out_size) {
    const float* x         = (const float*)d_in[0];
    const float* edge_attr = (const float*)d_in[1];
    const float* W1        = (const float*)d_in[2];
    const float* b1        = (const float*)d_in[3];
    const float* W2        = (const float*)d_in[4];
    const float* b2        = (const float*)d_in[5];
    const float* Wn        = (const float*)d_in[6];
    const float* bn        = (const float*)d_in[7];
    const int*   ei32      = (const int*)d_in[8];

    float* out    = (float*)d_out;
    const int write_logits = (out_size >= NN * CHW + EE);
    float* logits = out + (size_t)NN * CHW;

    cudaFuncSetAttribute(mlp_kernel,
                         cudaFuncAttributeMaxDynamicSharedMemorySize,
                         MLP_SMEM_BYTES);

    const int EB = (EE + 255) / 256;

    zero_kernel<<<(NSEG + 255) / 256, 256>>>(ei32);
    decode_kernel<<<EB, 256>>>(ei32);
    convx_kernel<<<NN * CHW / 4 / 256, 256>>>(x);
    mlp_kernel<<<EE / EPB, 256, MLP_SMEM_BYTES>>>(edge_attr, W1, b1, W2, b2,
                                                  logits, write_logits);
    scanA_kernel<<<NSCANB, 1024>>>();
    scanC_kernel<<<(NSEG + 255) / 256, 256>>>();
    fill_kernel<<<EB, 256>>>();
    fused_kernel<<<NN, 128>>>(x, Wn, bn, out);
}

// round 13
// speedup vs baseline: 1.1408x; 1.1129x over previous
#include <cuda_runtime.h>
#include <cuda_fp16.h>
#include <cstdint>
#include <math.h>

// Problem constants (fixed by the reference)
#define NN    10000
#define EE    160000
#define CC    16
#define CHW   1024       // C*H*W
#define DE    64         // edge feature dim
#define HID   128        // hidden dim
#define NSEG  (2 * NN)   // (node, dir) segments; dir 0 = out (r<c), 1 = in (r>c)
#define NSCANB ((NSEG + 1023) / 1024)   // 20 scan blocks

// ---------------------------------------------------------------------------
// Scratch (__device__ globals; no allocations allowed)
// ---------------------------------------------------------------------------
__device__ float g_sum_in [NN];
__device__ float g_sum_out[NN];
__device__ float g_exp[EE];
__device__ int   g_row[EE];
__device__ int   g_col[EE];
__device__ int   g_is64;
__device__ int   g_cnt[NSEG];
__device__ int   g_off[NSEG + 1];
__device__ int   g_pos[NSEG];
__device__ int   g_bsum[NSCANB];
__device__ int   g_scol[EE];       // col of sorted edge
__device__ float g_sw  [EE];       // softmax weight of sorted edge
__device__ __align__(16) __half g_xh[NN * CHW];   // fp16 copy of x (20.5 MB)

// ---------------------------------------------------------------------------
// Kernel 1: zero accumulators + (block 0) detect int64 vs int32 edge_index.
// ---------------------------------------------------------------------------
__global__ void zero_kernel(const int* __restrict__ v32) {
    int i = blockIdx.x * blockDim.x + threadIdx.x;
    if (i < NSEG) g_cnt[i] = 0;
    if (i < NN) { g_sum_in[i] = 0.f; g_sum_out[i] = 0.f; }
    if (blockIdx.x == 0 && threadIdx.x < 32) {
        int t = threadIdx.x;
        int nz = 0;
#pragma unroll
        for (int q = 0; q < 4; q++)
            nz |= (v32[2 * (t + q * 32) + 1] != 0);
#pragma unroll
        for (int s = 16; s > 0; s >>= 1)
            nz |= __shfl_xor_sync(0xffffffffu, nz, s);
        if (t == 0) g_is64 = nz ? 0 : 1;
    }
}

// ---------------------------------------------------------------------------
// Kernel 2: decode edge_index + segment histogram (merged)
// ---------------------------------------------------------------------------
__global__ void decode_kernel(const int* __restrict__ v32) {
    int e = blockIdx.x * blockDim.x + threadIdx.x;
    if (e >= EE) return;
    int r, c;
    if (g_is64) { r = v32[2 * e]; c = v32[2 * (EE + e)]; }
    else        { r = v32[e];     c = v32[EE + e]; }
    g_row[e] = r;
    g_col[e] = c;
    if (r != c) atomicAdd(&g_cnt[r * 2 + ((r < c) ? 0 : 1)], 1);
}

// ---------------------------------------------------------------------------
// Kernel 2b: convert x to fp16 (halves the fused-gather L2 traffic)
// ---------------------------------------------------------------------------
__global__ void convx_kernel(const float* __restrict__ x) {
    int i = blockIdx.x * blockDim.x + threadIdx.x;   // over NN*CHW/4
    float4 v = reinterpret_cast<const float4*>(x)[i];
    __half2 a = __floats2half2_rn(v.x, v.y);
    __half2 b = __floats2half2_rn(v.z, v.w);
    uint2 pk;
    pk.x = *reinterpret_cast<unsigned*>(&a);
    pk.y = *reinterpret_cast<unsigned*>(&b);
    reinterpret_cast<uint2*>(g_xh)[i] = pk;
}

// ---------------------------------------------------------------------------
// Kernel 3a: per-block local scan + block sums
// ---------------------------------------------------------------------------
__global__ void scanA_kernel() {      // NSCANB blocks x 1024
    __shared__ int wsum[32];
    const int t = threadIdx.x, lane = t & 31, wid = t >> 5;
    const int idx = blockIdx.x * 1024 + t;
    int v = (idx < NSEG) ? g_cnt[idx] : 0;
    int s = v;
#pragma unroll
    for (int off = 1; off < 32; off <<= 1) {
        int n = __shfl_up_sync(0xffffffffu, s, off);
        if (lane >= off) s += n;
    }
    if (lane == 31) wsum[wid] = s;
    __syncthreads();
    if (wid == 0) {
        int w = wsum[lane];
#pragma unroll
        for (int off = 1; off < 32; off <<= 1) {
            int n = __shfl_up_sync(0xffffffffu, w, off);
            if (lane >= off) w += n;
        }
        wsum[lane] = w;
    }
    __syncthreads();
    int incl = s + ((wid > 0) ? wsum[wid - 1] : 0);
    if (idx < NSEG) g_off[idx] = incl - v;       // local exclusive
    if (t == 1023) g_bsum[blockIdx.x] = incl;    // block total
}

// ---------------------------------------------------------------------------
// Kernel 3b: apply block offsets (each block re-scans the 20 block sums)
// ---------------------------------------------------------------------------
__global__ void scanC_kernel() {
    __shared__ int s_pre[NSCANB + 1];
    const int t = threadIdx.x;
    if (t < 32) {
        int v = (t < NSCANB) ? g_bsum[t] : 0;
        int s = v;
#pragma unroll
        for (int off = 1; off < 32; off <<= 1) {
            int n = __shfl_up_sync(0xffffffffu, s, off);
            if (t >= off) s += n;
        }
        if (t < NSCANB) s_pre[t] = s - v;       // exclusive
        if (t == 31)    s_pre[NSCANB] = s;      // grand total
    }
    __syncthreads();
    int idx = blockIdx.x * blockDim.x + t;
    if (idx < NSEG) {
        int o = g_off[idx] + s_pre[idx >> 10];
        g_off[idx] = o;
        g_pos[idx] = o;
    }
    if (idx == 0) g_off[NSEG] = s_pre[NSCANB];
}

// ---------------------------------------------------------------------------
// Kernel 4: edge MLP on the TENSOR pipe (mma.m16n8k16 f16->f32).
// EPB=128: 8 warps x 16 edges (1 m16-tile/warp). smem ~37.9KB -> 5 blocks/SM
// (40 warps/SM vs previous 16) to hide staging + MMA latency.
// ---------------------------------------------------------------------------
#define EPB 128
#define EAS 72                      // half stride per row (144B)
#define SM_W1T  0                   // [128][72] halfs = 18432 B
#define SM_EAS  18432               // [128][72] halfs = 18432 B
#define SM_B1   36864               // 128 floats
#define SM_W2   37376               // 128 floats
#define SM_B2   37888               // 1 float
#define MLP_SMEM_BYTES 37904

__device__ __forceinline__ unsigned smem_u32(const void* p) {
    return (unsigned)__cvta_generic_to_shared(p);
}

__global__ void __launch_bounds__(256)
mlp_kernel(const float* __restrict__ edge_attr,
           const float* __restrict__ W1,
           const float* __restrict__ b1,
           const float* __restrict__ W2,
           const float* __restrict__ b2,
           float* __restrict__ logits,
           int write_logits) {
    extern __shared__ char smemraw[];
    __half* W1T = reinterpret_cast<__half*>(smemraw + SM_W1T);
    __half* eas = reinterpret_cast<__half*>(smemraw + SM_EAS);
    float*  b1s = reinterpret_cast<float*>(smemraw + SM_B1);
    float*  W2s = reinterpret_cast<float*>(smemraw + SM_W2);
    float*  b2s = reinterpret_cast<float*>(smemraw + SM_B2);

    const int t = threadIdx.x;

    // Stage W1 transposed as fp16: W1T[n][k] = W1[k][n]
    for (int i = t; i < DE * HID; i += 256) {
        int k = i >> 7, n = i & 127;
        W1T[n * EAS + k] = __float2half_rn(W1[i]);
    }
    if (t < 128) { b1s[t] = b1[t]; W2s[t] = W2[t]; }
    if (t == 0)  b2s[0] = b2[0];

    // Stage 128 edges of edge_attr as fp16, stride-72 rows
    const float4* ea4 = reinterpret_cast<const float4*>(
        edge_attr + (size_t)blockIdx.x * EPB * DE);
    for (int i = t; i < EPB * DE / 4; i += 256) {
        float4 v = ea4[i];
        int ed = i >> 4;            // 16 float4 per edge
        int k4 = i & 15;
        __half2 h01 = __floats2half2_rn(v.x, v.y);
        __half2 h23 = __floats2half2_rn(v.z, v.w);
        uint2 pk;
        pk.x = *reinterpret_cast<unsigned*>(&h01);
        pk.y = *reinterpret_cast<unsigned*>(&h23);
        *reinterpret_cast<uint2*>(eas + ed * EAS + k4 * 4) = pk;
    }
    __syncthreads();

    const int wid  = t >> 5;
    const int lane = t & 31;
    const int gid  = lane >> 2;     // 0..7
    const int tig  = lane & 3;      // 0..3
    const int ebase = wid * 16;     // this warp's 16 edges (1 m16-tile)

    // Load A fragments: [4 k-chunks][4 regs] via ldmatrix.x4
    unsigned afr[4][4];
    const int arow  = ebase + (lane & 15);
    const int acolh = (lane >> 4) * 8;
#pragma unroll
    for (int kc = 0; kc < 4; kc++) {
        unsigned addr = smem_u32(&eas[arow * EAS + kc * 16 + acolh]);
        asm volatile(
            "ldmatrix.sync.aligned.m8n8.x4.shared.b16 {%0,%1,%2,%3}, [%4];"
            : "=r"(afr[kc][0]), "=r"(afr[kc][1]),
              "=r"(afr[kc][2]), "=r"(afr[kc][3])
            : "r"(addr));
    }

    float lp[2] = {0.f, 0.f};       // [rowhalf]

#pragma unroll 4
    for (int nt = 0; nt < 16; nt++) {
        // B fragments for this n-tile: conflict-free LDS.32 from W1T
        const __half* wb = &W1T[(nt * 8 + gid) * EAS];
        unsigned bfr[4][2];
#pragma unroll
        for (int kc = 0; kc < 4; kc++) {
            bfr[kc][0] = *reinterpret_cast<const unsigned*>(
                wb + kc * 16 + 2 * tig);
            bfr[kc][1] = *reinterpret_cast<const unsigned*>(
                wb + kc * 16 + 2 * tig + 8);
        }
        const int colb = nt * 8 + tig * 2;
        float b1a = b1s[colb],  b1b = b1s[colb + 1];
        float w2a = W2s[colb],  w2b = W2s[colb + 1];

        // two independent kc-chains -> 2x MMA parallelism
        float a0 = 0.f, a1 = 0.f, a2 = 0.f, a3 = 0.f;   // kc 0,1
        float d0 = 0.f, d1 = 0.f, d2 = 0.f, d3 = 0.f;   // kc 2,3
#pragma unroll
        for (int kc = 0; kc < 2; kc++) {
            asm volatile(
                "mma.sync.aligned.m16n8k16.row.col.f32.f16.f16.f32 "
                "{%0,%1,%2,%3}, {%4,%5,%6,%7}, {%8,%9}, {%0,%1,%2,%3};"
                : "+f"(a0), "+f"(a1), "+f"(a2), "+f"(a3)
                : "r"(afr[kc][0]), "r"(afr[kc][1]),
                  "r"(afr[kc][2]), "r"(afr[kc][3]),
                  "r"(bfr[kc][0]), "r"(bfr[kc][1]));
            asm volatile(
                "mma.sync.aligned.m16n8k16.row.col.f32.f16.f16.f32 "
                "{%0,%1,%2,%3}, {%4,%5,%6,%7}, {%8,%9}, {%0,%1,%2,%3};"
                : "+f"(d0), "+f"(d1), "+f"(d2), "+f"(d3)
                : "r"(afr[kc + 2][0]), "r"(afr[kc + 2][1]),
                  "r"(afr[kc + 2][2]), "r"(afr[kc + 2][3]),
                  "r"(bfr[kc + 2][0]), "r"(bfr[kc + 2][1]));
        }
        float c0 = a0 + d0, c1 = a1 + d1;
        float c2 = a2 + d2, c3 = a3 + d3;
        lp[0] += fmaxf(c0 + b1a, 0.f) * w2a + fmaxf(c1 + b1b, 0.f) * w2b;
        lp[1] += fmaxf(c2 + b1a, 0.f) * w2a + fmaxf(c3 + b1b, 0.f) * w2b;
    }

    // Reduce across the 4-thread quad (tig dimension)
#pragma unroll
    for (int s = 1; s <= 2; s <<= 1) {
        lp[0] += __shfl_xor_sync(0xffffffffu, lp[0], s);
        lp[1] += __shfl_xor_sync(0xffffffffu, lp[1], s);
    }

    if (tig == 0) {
        float bb = b2s[0];
#pragma unroll
        for (int h = 0; h < 2; h++) {
            int e = blockIdx.x * EPB + ebase + h * 8 + gid;
            float logit = lp[h] + bb;
            if (write_logits) logits[e] = logit;
            float ex = expf(logit);
            g_exp[e] = ex;
            int r = g_row[e], c = g_col[e];
            if (r < c)      atomicAdd(&g_sum_out[r], ex);
            else if (r > c) atomicAdd(&g_sum_in[r],  ex);
        }
    }
}

// ---------------------------------------------------------------------------
// Kernel 5: fill CSR lists with final softmax weights (sums ready post-MLP)
// ---------------------------------------------------------------------------
__global__ void fill_kernel() {
    int e = blockIdx.x * blockDim.x + threadIdx.x;
    if (e >= EE) return;
    int r = g_row[e], c = g_col[e];
    if (r == c) return;
    int dirin = (r > c);
    int seg = r * 2 + dirin;
    int pos = atomicAdd(&g_pos[seg], 1);
    float sum = dirin ? g_sum_in[r] : g_sum_out[r];
    g_scol[pos] = c;
    g_sw[pos]   = g_exp[e] / fmaxf(sum, 1e-30f);
}

// ---------------------------------------------------------------------------
// Kernel 6: fused gather + 1x1 conv, v3: WARP-PER-SEGMENT.
// Block = 256 threads = 8 warps = 4 nodes x 2 dirs. Each warp walks its
// (node,dir) edge list with NO barriers; each lane issues 4 independent
// uint4 loads per edge (8+ in flight with unroll 2). Flow kept in regs
// (32 floats/lane), dumped to smem once, then conv epilogue.
// ---------------------------------------------------------------------------
#define NPB 4

__global__ void __launch_bounds__(256)
fused_kernel(const float* __restrict__ x,
             const float* __restrict__ Wn,
             const float* __restrict__ bn,
             float* __restrict__ out) {
    __shared__ float s_flow[NPB * 2 * CHW];   // [ni*2+dir][1024] = 32KB
    __shared__ float WsT[48 * 16];            // WsT[cc][o] = Wn[o*48+cc]
    __shared__ float bs[16];

    const int t    = threadIdx.x;
    const int warp = t >> 5;
    const int lane = t & 31;

    for (int i = t; i < 768; i += 256) {
        int o = i / 48, cc = i % 48;
        WsT[cc * 16 + o] = Wn[i];
    }
    if (t < 16) bs[t] = bn[t];

    // ---- gather: warp owns segment (node, dir) ----
    const int ni   = warp >> 1;
    const int dir  = warp & 1;
    const int node = blockIdx.x * NPB + ni;
    const int seg  = node * 2 + dir;
    const int lo = g_off[seg];
    const int hi = g_off[seg + 1];

    // lane owns uint4s {lane, lane+32, lane+64, lane+96} of each node tile
    const uint4* xh = reinterpret_cast<const uint4*>(g_xh);

    float acc[4][8];
#pragma unroll
    for (int k = 0; k < 4; k++)
#pragma unroll
        for (int j = 0; j < 8; j++) acc[k][j] = 0.f;

#pragma unroll 2
    for (int e = lo; e < hi; e++) {
        float w   = __ldg(&g_sw[e]);      // warp-uniform
        int   col = __ldg(&g_scol[e]);    // warp-uniform
        const uint4* xp = xh + (size_t)col * 128 + lane;
#pragma unroll
        for (int k = 0; k < 4; k++) {
            uint4 hv = __ldg(xp + k * 32);
            unsigned u[4] = {hv.x, hv.y, hv.z, hv.w};
#pragma unroll
            for (int q = 0; q < 4; q++) {
                __half2 h = *reinterpret_cast<__half2*>(&u[q]);
                float2 f = __half22float2(h);
                acc[k][q*2]   += w * f.x;
                acc[k][q*2+1] += w * f.y;
            }
        }
    }

    // dump flow to smem: element index of acc[k][j] is (k*32+lane)*8 + j
    float* fl = s_flow + (ni * 2 + dir) * CHW;
#pragma unroll
    for (int k = 0; k < 4; k++) {
#pragma unroll
        for (int p = 0; p < 2; p++) {
            reinterpret_cast<float4*>(fl)[(k * 32 + lane) * 2 + p] =
                make_float4(acc[k][p*4], acc[k][p*4+1],
                            acc[k][p*4+2], acc[k][p*4+3]);
        }
    }
    __syncthreads();

    // ---- conv: 64 threads per node, thread = one hw, all 16 outputs ----
    const int ni2  = t >> 6;
    const int hw   = t & 63;
    const int node2 = blockIdx.x * NPB + ni2;
    const float* fo = s_flow + (ni2 * 2 + 0) * CHW;   // dir 0 = out (r<c)
    const float* fi = s_flow + (ni2 * 2 + 1) * CHW;   // dir 1 = in  (r>c)

    float a[16];
#pragma unroll
    for (int o = 0; o < 16; o++) a[o] = bs[o];

    const float* xb = x + (size_t)node2 * CHW;
#pragma unroll 4
    for (int cc = 0; cc < 16; cc++) {
        float vx = __ldg(&xb[cc * 64 + hw]);
        float vi = fi[cc * 64 + hw];
        float vo = fo[cc * 64 + hw];
#pragma unroll
        for (int m = 0; m < 4; m++) {
            float4 wx = reinterpret_cast<const float4*>(&WsT[(cc)      * 16])[m];
            float4 wi = reinterpret_cast<const float4*>(&WsT[(16 + cc) * 16])[m];
            float4 wo = reinterpret_cast<const float4*>(&WsT[(32 + cc) * 16])[m];
            a[m*4+0] += vx * wx.x + vi * wi.x + vo * wo.x;
            a[m*4+1] += vx * wx.y + vi * wi.y + vo * wo.y;
            a[m*4+2] += vx * wx.z + vi * wi.z + vo * wo.z;
            a[m*4+3] += vx * wx.w + vi * wi.w + vo * wo.w;
        }
    }

    float* ob = out + (size_t)node2 * CHW;
#pragma unroll
    for (int o = 0; o < 16; o++)
        ob[o * 64 + hw] = a[o];
}

// ---------------------------------------------------------------------------
// Launch (default stream; sequentially ordered; graph-capturable)
// MLP stays the 4th launch so ncu samples it.
// ---------------------------------------------------------------------------
extern "C" void kernel_launch(void* const* d_in, const int* in_sizes, int n_in,
                              void* d_out, int out_size) {
    const float* x         = (const float*)d_in[0];
    const float* edge_attr = (const float*)d_in[1];
    const float* W1        = (const float*)d_in[2];
    const float* b1        = (const float*)d_in[3];
    const float* W2        = (const float*)d_in[4];
    const float* b2        = (const float*)d_in[5];
    const float* Wn        = (const float*)d_in[6];
    const float* bn        = (const float*)d_in[7];
    const int*   ei32      = (const int*)d_in[8];

    float* out    = (float*)d_out;
    const int write_logits = (out_size >= NN * CHW + EE);
    float* logits = out + (size_t)NN * CHW;

    cudaFuncSetAttribute(mlp_kernel,
                         cudaFuncAttributeMaxDynamicSharedMemorySize,
                         MLP_SMEM_BYTES);

    const int EB = (EE + 255) / 256;

    zero_kernel<<<(NSEG + 255) / 256, 256>>>(ei32);
    decode_kernel<<<EB, 256>>>(ei32);
    convx_kernel<<<NN * CHW / 4 / 256, 256>>>(x);
    mlp_kernel<<<EE / EPB, 256, MLP_SMEM_BYTES>>>(edge_attr, W1, b1, W2, b2,
                                                  logits, write_logits);
    scanA_kernel<<<NSCANB, 1024>>>();
    scanC_kernel<<<(NSEG + 255) / 256, 256>>>();
    fill_kernel<<<EB, 256>>>();
    fused_kernel<<<NN / NPB, 256>>>(x, Wn, bn, out);
}

// round 14
// speedup vs baseline: 1.1739x; 1.0290x over previous
#include <cuda_runtime.h>
#include <cuda_fp16.h>
#include <cstdint>
#include <math.h>

// Problem constants (fixed by the reference)
#define NN    10000
#define EE    160000
#define CC    16
#define CHW   1024       // C*H*W
#define DE    64         // edge feature dim
#define HID   128        // hidden dim
#define NSEG  (2 * NN)   // (node, dir) segments; dir 0 = out (r<c), 1 = in (r>c)
#define NSCANB ((NSEG + 1023) / 1024)   // 20 scan blocks

// ---------------------------------------------------------------------------
// Scratch (__device__ globals; no allocations allowed)
// ---------------------------------------------------------------------------
__device__ float g_sum_in [NN];
__device__ float g_sum_out[NN];
__device__ float g_exp[EE];
__device__ int   g_row[EE];
__device__ int   g_col[EE];
__device__ int   g_is64;
__device__ int   g_cnt[NSEG];
__device__ int   g_off[NSEG + 1];
__device__ int   g_pos[NSEG];
__device__ int   g_bsum[NSCANB];
__device__ int   g_scol[EE];       // col of sorted edge
__device__ float g_sw  [EE];       // softmax weight of sorted edge

// ---------------------------------------------------------------------------
// f32x2 packed helpers: 2 fp32 FMAs per issue slot.
// ---------------------------------------------------------------------------
__device__ __forceinline__ unsigned long long ffma2(unsigned long long a,
                                                    unsigned long long b,
                                                    unsigned long long c) {
    unsigned long long d;
    asm("fma.rn.f32x2 %0, %1, %2, %3;" : "=l"(d) : "l"(a), "l"(b), "l"(c));
    return d;
}
__device__ __forceinline__ unsigned long long pack2(float a) {
    unsigned long long r;
    unsigned int u = __float_as_uint(a);
    asm("mov.b64 %0, {%1, %1};" : "=l"(r) : "r"(u));
    return r;
}

// ---------------------------------------------------------------------------
// Kernel 1: zero accumulators + (block 0) detect int64 vs int32 edge_index.
// ---------------------------------------------------------------------------
__global__ void zero_kernel(const int* __restrict__ v32) {
    int i = blockIdx.x * blockDim.x + threadIdx.x;
    if (i < NSEG) g_cnt[i] = 0;
    if (i < NN) { g_sum_in[i] = 0.f; g_sum_out[i] = 0.f; }
    if (blockIdx.x == 0 && threadIdx.x < 32) {
        int t = threadIdx.x;
        int nz = 0;
#pragma unroll
        for (int q = 0; q < 4; q++)
            nz |= (v32[2 * (t + q * 32) + 1] != 0);
#pragma unroll
        for (int s = 16; s > 0; s >>= 1)
            nz |= __shfl_xor_sync(0xffffffffu, nz, s);
        if (t == 0) g_is64 = nz ? 0 : 1;
    }
}

// ---------------------------------------------------------------------------
// Kernel 2: decode edge_index + segment histogram (merged)
// ---------------------------------------------------------------------------
__global__ void decode_kernel(const int* __restrict__ v32) {
    int e = blockIdx.x * blockDim.x + threadIdx.x;
    if (e >= EE) return;
    int r, c;
    if (g_is64) { r = v32[2 * e]; c = v32[2 * (EE + e)]; }
    else        { r = v32[e];     c = v32[EE + e]; }
    g_row[e] = r;
    g_col[e] = c;
    if (r != c) atomicAdd(&g_cnt[r * 2 + ((r < c) ? 0 : 1)], 1);
}

// ---------------------------------------------------------------------------
// Kernel 3a: per-block local scan + block sums
// ---------------------------------------------------------------------------
__global__ void scanA_kernel() {      // NSCANB blocks x 1024
    __shared__ int wsum[32];
    const int t = threadIdx.x, lane = t & 31, wid = t >> 5;
    const int idx = blockIdx.x * 1024 + t;
    int v = (idx < NSEG) ? g_cnt[idx] : 0;
    int s = v;
#pragma unroll
    for (int off = 1; off < 32; off <<= 1) {
        int n = __shfl_up_sync(0xffffffffu, s, off);
        if (lane >= off) s += n;
    }
    if (lane == 31) wsum[wid] = s;
    __syncthreads();
    if (wid == 0) {
        int w = wsum[lane];
#pragma unroll
        for (int off = 1; off < 32; off <<= 1) {
            int n = __shfl_up_sync(0xffffffffu, w, off);
            if (lane >= off) w += n;
        }
        wsum[lane] = w;
    }
    __syncthreads();
    int incl = s + ((wid > 0) ? wsum[wid - 1] : 0);
    if (idx < NSEG) g_off[idx] = incl - v;       // local exclusive
    if (t == 1023) g_bsum[blockIdx.x] = incl;    // block total
}

// ---------------------------------------------------------------------------
// Kernel 3b: apply block offsets (each block re-scans the 20 block sums)
// ---------------------------------------------------------------------------
__global__ void scanC_kernel() {
    __shared__ int s_pre[NSCANB + 1];
    const int t = threadIdx.x;
    if (t < 32) {
        int v = (t < NSCANB) ? g_bsum[t] : 0;
        int s = v;
#pragma unroll
        for (int off = 1; off < 32; off <<= 1) {
            int n = __shfl_up_sync(0xffffffffu, s, off);
            if (t >= off) s += n;
        }
        if (t < NSCANB) s_pre[t] = s - v;       // exclusive
        if (t == 31)    s_pre[NSCANB] = s;      // grand total
    }
    __syncthreads();
    int idx = blockIdx.x * blockDim.x + t;
    if (idx < NSEG) {
        int o = g_off[idx] + s_pre[idx >> 10];
        g_off[idx] = o;
        g_pos[idx] = o;
    }
    if (idx == 0) g_off[NSEG] = s_pre[NSCANB];
}

// ---------------------------------------------------------------------------
// Kernel 4: edge MLP on the TENSOR pipe (mma.m16n8k16 f16->f32).
// EPB=128: 8 warps x 16 edges; ~37.9KB smem -> 5 blocks/SM.
// ---------------------------------------------------------------------------
#define EPB 128
#define EAS 72                      // half stride per row (144B)
#define SM_W1T  0                   // [128][72] halfs = 18432 B
#define SM_EAS  18432               // [128][72] halfs = 18432 B
#define SM_B1   36864               // 128 floats
#define SM_W2   37376               // 128 floats
#define SM_B2   37888               // 1 float
#define MLP_SMEM_BYTES 37904

__device__ __forceinline__ unsigned smem_u32(const void* p) {
    return (unsigned)__cvta_generic_to_shared(p);
}

__global__ void __launch_bounds__(256)
mlp_kernel(const float* __restrict__ edge_attr,
           const float* __restrict__ W1,
           const float* __restrict__ b1,
           const float* __restrict__ W2,
           const float* __restrict__ b2,
           float* __restrict__ logits,
           int write_logits) {
    extern __shared__ char smemraw[];
    __half* W1T = reinterpret_cast<__half*>(smemraw + SM_W1T);
    __half* eas = reinterpret_cast<__half*>(smemraw + SM_EAS);
    float*  b1s = reinterpret_cast<float*>(smemraw + SM_B1);
    float*  W2s = reinterpret_cast<float*>(smemraw + SM_W2);
    float*  b2s = reinterpret_cast<float*>(smemraw + SM_B2);

    const int t = threadIdx.x;

    for (int i = t; i < DE * HID; i += 256) {
        int k = i >> 7, n = i & 127;
        W1T[n * EAS + k] = __float2half_rn(W1[i]);
    }
    if (t < 128) { b1s[t] = b1[t]; W2s[t] = W2[t]; }
    if (t == 0)  b2s[0] = b2[0];

    const float4* ea4 = reinterpret_cast<const float4*>(
        edge_attr + (size_t)blockIdx.x * EPB * DE);
    for (int i = t; i < EPB * DE / 4; i += 256) {
        float4 v = ea4[i];
        int ed = i >> 4;
        int k4 = i & 15;
        __half2 h01 = __floats2half2_rn(v.x, v.y);
        __half2 h23 = __floats2half2_rn(v.z, v.w);
        uint2 pk;
        pk.x = *reinterpret_cast<unsigned*>(&h01);
        pk.y = *reinterpret_cast<unsigned*>(&h23);
        *reinterpret_cast<uint2*>(eas + ed * EAS + k4 * 4) = pk;
    }
    __syncthreads();

    const int wid  = t >> 5;
    const int lane = t & 31;
    const int gid  = lane >> 2;
    const int tig  = lane & 3;
    const int ebase = wid * 16;

    unsigned afr[4][4];
    const int arow  = ebase + (lane & 15);
    const int acolh = (lane >> 4) * 8;
#pragma unroll
    for (int kc = 0; kc < 4; kc++) {
        unsigned addr = smem_u32(&eas[arow * EAS + kc * 16 + acolh]);
        asm volatile(
            "ldmatrix.sync.aligned.m8n8.x4.shared.b16 {%0,%1,%2,%3}, [%4];"
            : "=r"(afr[kc][0]), "=r"(afr[kc][1]),
              "=r"(afr[kc][2]), "=r"(afr[kc][3])
            : "r"(addr));
    }

    float lp[2] = {0.f, 0.f};

#pragma unroll 4
    for (int nt = 0; nt < 16; nt++) {
        const __half* wb = &W1T[(nt * 8 + gid) * EAS];
        unsigned bfr[4][2];
#pragma unroll
        for (int kc = 0; kc < 4; kc++) {
            bfr[kc][0] = *reinterpret_cast<const unsigned*>(
                wb + kc * 16 + 2 * tig);
            bfr[kc][1] = *reinterpret_cast<const unsigned*>(
                wb + kc * 16 + 2 * tig + 8);
        }
        const int colb = nt * 8 + tig * 2;
        float b1a = b1s[colb],  b1b = b1s[colb + 1];
        float w2a = W2s[colb],  w2b = W2s[colb + 1];

        float a0 = 0.f, a1 = 0.f, a2 = 0.f, a3 = 0.f;
        float d0 = 0.f, d1 = 0.f, d2 = 0.f, d3 = 0.f;
#pragma unroll
        for (int kc = 0; kc < 2; kc++) {
            asm volatile(
                "mma.sync.aligned.m16n8k16.row.col.f32.f16.f16.f32 "
                "{%0,%1,%2,%3}, {%4,%5,%6,%7}, {%8,%9}, {%0,%1,%2,%3};"
                : "+f"(a0), "+f"(a1), "+f"(a2), "+f"(a3)
                : "r"(afr[kc][0]), "r"(afr[kc][1]),
                  "r"(afr[kc][2]), "r"(afr[kc][3]),
                  "r"(bfr[kc][0]), "r"(bfr[kc][1]));
            asm volatile(
                "mma.sync.aligned.m16n8k16.row.col.f32.f16.f16.f32 "
                "{%0,%1,%2,%3}, {%4,%5,%6,%7}, {%8,%9}, {%0,%1,%2,%3};"
                : "+f"(d0), "+f"(d1), "+f"(d2), "+f"(d3)
                : "r"(afr[kc + 2][0]), "r"(afr[kc + 2][1]),
                  "r"(afr[kc + 2][2]), "r"(afr[kc + 2][3]),
                  "r"(bfr[kc + 2][0]), "r"(bfr[kc + 2][1]));
        }
        float c0 = a0 + d0, c1 = a1 + d1;
        float c2 = a2 + d2, c3 = a3 + d3;
        lp[0] += fmaxf(c0 + b1a, 0.f) * w2a + fmaxf(c1 + b1b, 0.f) * w2b;
        lp[1] += fmaxf(c2 + b1a, 0.f) * w2a + fmaxf(c3 + b1b, 0.f) * w2b;
    }

#pragma unroll
    for (int s = 1; s <= 2; s <<= 1) {
        lp[0] += __shfl_xor_sync(0xffffffffu, lp[0], s);
        lp[1] += __shfl_xor_sync(0xffffffffu, lp[1], s);
    }

    if (tig == 0) {
        float bb = b2s[0];
#pragma unroll
        for (int h = 0; h < 2; h++) {
            int e = blockIdx.x * EPB + ebase + h * 8 + gid;
            float logit = lp[h] + bb;
            if (write_logits) logits[e] = logit;
            float ex = expf(logit);
            g_exp[e] = ex;
            int r = g_row[e], c = g_col[e];
            if (r < c)      atomicAdd(&g_sum_out[r], ex);
            else if (r > c) atomicAdd(&g_sum_in[r],  ex);
        }
    }
}

// ---------------------------------------------------------------------------
// Kernel 5: fill CSR lists with final softmax weights (sums ready post-MLP)
// ---------------------------------------------------------------------------
__global__ void fill_kernel() {
    int e = blockIdx.x * blockDim.x + threadIdx.x;
    if (e >= EE) return;
    int r = g_row[e], c = g_col[e];
    if (r == c) return;
    int dirin = (r > c);
    int seg = r * 2 + dirin;
    int pos = atomicAdd(&g_pos[seg], 1);
    float sum = dirin ? g_sum_in[r] : g_sum_out[r];
    g_scol[pos] = c;
    g_sw[pos]   = g_exp[e] / fmaxf(sum, 1e-30f);
}

// ---------------------------------------------------------------------------
// Kernel 6: fused gather + 1x1 conv, v4: ALL-PACKED f32x2 MATH.
// Block = 256 threads = 8 warps = 2 nodes x 2 dirs x 2 edge-halves.
// Gather: fp32 x directly (no conversions!): per edge-warp 8 LDG.128 +
// 16 FFMA2. Two warps split each segment's edges; halves summed in conv.
// Conv: 128 threads/node = 64 hw x 2 output-halves; f32x2 over output
// pairs: 12 FFMA2 + 6 weight-LDS.128 per cc per thread.
// ---------------------------------------------------------------------------
#define NPB 2

__global__ void __launch_bounds__(256, 3)
fused_kernel(const float* __restrict__ x,
             const float* __restrict__ Wn,
             const float* __restrict__ bn,
             float* __restrict__ out) {
    // [ni][dir][half][1024] floats = 32KB
    __shared__ __align__(16) float s_flow[NPB * 2 * 2 * CHW];
    __shared__ __align__(16) float WsT[48 * 16];  // WsT[cc][o] = Wn[o*48+cc]
    __shared__ __align__(16) float bs[16];

    const int t    = threadIdx.x;
    const int warp = t >> 5;
    const int lane = t & 31;

    for (int i = t; i < 768; i += 256) {
        int o = i / 48, cc = i % 48;
        WsT[cc * 16 + o] = Wn[i];
    }
    if (t < 16) bs[t] = bn[t];

    // ---- gather ----
    const int segIdx = warp >> 1;          // 0..3: ni*2+dir
    const int half   = warp & 1;
    const int ni     = segIdx >> 1;
    const int dir    = segIdx & 1;
    const int node   = blockIdx.x * NPB + ni;
    const int seg    = node * 2 + dir;
    const int lo = g_off[seg];
    const int hi = g_off[seg + 1];

    // lane owns ulonglong2 (16B) slots {lane, lane+32, ..., lane+224}
    const ulonglong2* xq = reinterpret_cast<const ulonglong2*>(x);

    unsigned long long A[16];
#pragma unroll
    for (int k = 0; k < 16; k++) A[k] = 0ull;

    for (int e = lo + half; e < hi; e += 2) {
        unsigned long long w2 = pack2(__ldg(&g_sw[e]));
        int col = __ldg(&g_scol[e]);
        const ulonglong2* xp = xq + (size_t)col * 256 + lane;
#pragma unroll
        for (int k = 0; k < 8; k++) {
            ulonglong2 v = __ldg(xp + k * 32);
            A[2*k]   = ffma2(w2, v.x, A[2*k]);
            A[2*k+1] = ffma2(w2, v.y, A[2*k+1]);
        }
    }

    // dump: float4 slot (k*32+lane) of this (ni,dir,half) flow buffer
    {
        ulonglong2* fl = reinterpret_cast<ulonglong2*>(
            s_flow + (size_t)(segIdx * 2 + half) * CHW);
#pragma unroll
        for (int k = 0; k < 8; k++) {
            ulonglong2 v;
            v.x = A[2*k]; v.y = A[2*k+1];
            fl[k * 32 + lane] = v;
        }
    }
    __syncthreads();

    // ---- conv: 128 threads/node = 64 hw x 2 output halves ----
    const int ni2 = t >> 7;               // 0..1
    const int r   = t & 127;
    const int og  = r >> 6;               // output half: o in [og*8, og*8+8)
    const int hw  = r & 63;
    const int node2 = blockIdx.x * NPB + ni2;

    const float* fo0 = s_flow + (size_t)((ni2 * 2 + 0) * 2 + 0) * CHW;
    const float* fo1 = s_flow + (size_t)((ni2 * 2 + 0) * 2 + 1) * CHW;
    const float* fi0 = s_flow + (size_t)((ni2 * 2 + 1) * 2 + 0) * CHW;
    const float* fi1 = s_flow + (size_t)((ni2 * 2 + 1) * 2 + 1) * CHW;

    unsigned long long a[4];
    {
        const unsigned long long* b2p =
            reinterpret_cast<const unsigned long long*>(bs);
#pragma unroll
        for (int j = 0; j < 4; j++) a[j] = b2p[og * 4 + j];
    }

    const float* xb = x + (size_t)node2 * CHW;
#pragma unroll 4
    for (int cc = 0; cc < 16; cc++) {
        int idx = cc * 64 + hw;
        float vx = __ldg(&xb[idx]);
        float vi = fi0[idx] + fi1[idx];
        float vo = fo0[idx] + fo1[idx];
        unsigned long long vx2 = pack2(vx);
        unsigned long long vi2 = pack2(vi);
        unsigned long long vo2 = pack2(vo);
        const unsigned long long* wx =
            reinterpret_cast<const unsigned long long*>(
                &WsT[(cc)      * 16 + og * 8]);
        const unsigned long long* wi =
            reinterpret_cast<const unsigned long long*>(
                &WsT[(16 + cc) * 16 + og * 8]);
        const unsigned long long* wo =
            reinterpret_cast<const unsigned long long*>(
                &WsT[(32 + cc) * 16 + og * 8]);
#pragma unroll
        for (int j = 0; j < 4; j++) {
            a[j] = ffma2(vx2, wx[j], a[j]);
            a[j] = ffma2(vi2, wi[j], a[j]);
            a[j] = ffma2(vo2, wo[j], a[j]);
        }
    }

    float* ob = out + (size_t)node2 * CHW;
#pragma unroll
    for (int j = 0; j < 4; j++) {
        float2 f = *reinterpret_cast<float2*>(&a[j]);
        ob[(og * 8 + 2*j)     * 64 + hw] = f.x;
        ob[(og * 8 + 2*j + 1) * 64 + hw] = f.y;
    }
}

// ---------------------------------------------------------------------------
// Launch (default stream; sequentially ordered; graph-capturable)
// MLP is the 4th launch (profiled slot): zero, decode, scanA, MLP, scanC,
// fill, fused. scanA only needs decode; mlp only needs decode.
// ---------------------------------------------------------------------------
extern "C" void kernel_launch(void* const* d_in, const int* in_sizes, int n_in,
                              void* d_out, int out_size) {
    const float* x         = (const float*)d_in[0];
    const float* edge_attr = (const float*)d_in[1];
    const float* W1        = (const float*)d_in[2];
    const float* b1        = (const float*)d_in[3];
    const float* W2        = (const float*)d_in[4];
    const float* b2        = (const float*)d_in[5];
    const float* Wn        = (const float*)d_in[6];
    const float* bn        = (const float*)d_in[7];
    const int*   ei32      = (const int*)d_in[8];

    float* out    = (float*)d_out;
    const int write_logits = (out_size >= NN * CHW + EE);
    float* logits = out + (size_t)NN * CHW;

    cudaFuncSetAttribute(mlp_kernel,
                         cudaFuncAttributeMaxDynamicSharedMemorySize,
                         MLP_SMEM_BYTES);

    const int EB = (EE + 255) / 256;

    zero_kernel<<<(NSEG + 255) / 256, 256>>>(ei32);
    decode_kernel<<<EB, 256>>>(ei32);
    scanA_kernel<<<NSCANB, 1024>>>();
    mlp_kernel<<<EE / EPB, 256, MLP_SMEM_BYTES>>>(edge_attr, W1, b1, W2, b2,
                                                  logits, write_logits);
    scanC_kernel<<<(NSEG + 255) / 256, 256>>>();
    fill_kernel<<<EB, 256>>>();
    fused_kernel<<<NN / NPB, 256>>>(x, Wn, bn, out);
}